// round 8
// baseline (speedup 1.0000x reference)
#include <cuda_runtime.h>
#include <math.h>

#define NMAX 100000
#define EMAX 3200000

// ---------------- device scratch (static, no allocs) ------------------------
__device__ int   g_is64;
__device__ __align__(8) int2 g_edge[EMAX];        // (src, dst)
__device__ int   g_deg[NMAX];                     // 1 + in-degree
__device__ float g_dinv[NMAX];
__device__ __align__(16) float g_t1[NMAX * 16];   // (x@W1)*dinv
__device__ __align__(16) float g_a1[NMAX * 16];   // layer-1 accumulator
__device__ __align__(8)  float g_t2[NMAX * 2];    // (h@W2)*dinv
__device__ __align__(8)  float g_a2[NMAX * 2];    // layer-2 accumulator

__device__ __forceinline__ void red_add_v4(float* p, float4 v) {
    asm volatile("red.global.add.v4.f32 [%0], {%1,%2,%3,%4};"
                 :: "l"(p), "f"(v.x), "f"(v.y), "f"(v.z), "f"(v.w) : "memory");
}
__device__ __forceinline__ void red_add_v2(float* p, float2 v) {
    asm volatile("red.global.add.v2.f32 [%0], {%1,%2};"
                 :: "l"(p), "f"(v.x), "f"(v.y) : "memory");
}

// ---------------------------------------------------------------------------
__global__ void k_detect(const int* __restrict__ ei32) {
    if (threadIdx.x == 0 && blockIdx.x == 0) {
        int all0 = 1;
        for (int i = 0; i < 64; i++)
            if (ei32[2 * i + 1] != 0) { all0 = 0; break; }
        g_is64 = all0;
    }
}

__global__ void k_deg_init(int N) {
    int i = blockIdx.x * blockDim.x + threadIdx.x;
    if (i < N) g_deg[i] = 1;
}

// convert edge indices -> int2, count degrees on dst
__global__ void k_convert(const void* __restrict__ ei, int E, int N) {
    int e = blockIdx.x * blockDim.x + threadIdx.x;
    if (e >= E) return;
    int s, d;
    if (g_is64) {
        const long long* p = (const long long*)ei;
        s = (int)p[e];
        d = (int)p[(long long)E + e];
    } else {
        const int* p = (const int*)ei;
        s = p[e];
        d = p[E + e];
    }
    if ((unsigned)s >= (unsigned)N) s = 0;
    if ((unsigned)d >= (unsigned)N) d = 0;
    g_edge[e] = make_int2(s, d);
    atomicAdd(&g_deg[d], 1);
}

// ---------------- GEMM1: warp-cooperative, W in registers -------------------
// lane = (kg, jg): kg = lane&7 owns k in [16kg,16kg+16); jg = lane>>3 owns
// j in [4jg, 4jg+4). W slice (16x4 = 64 regs) loaded once per warp.
// x read fully coalesced. kg-octet reduced via 3-step butterfly shuffle.
// Each warp processes NPW nodes (2 per iteration).
#define NPW 16
#define FMA4(acc, xv, wv)                \
    acc.x = fmaf(xv, wv.x, acc.x);       \
    acc.y = fmaf(xv, wv.y, acc.y);       \
    acc.z = fmaf(xv, wv.z, acc.z);       \
    acc.w = fmaf(xv, wv.w, acc.w);

__device__ __forceinline__ void bfly4(float4& a) {
#pragma unroll
    for (int s = 1; s < 8; s <<= 1) {
        a.x += __shfl_xor_sync(0xffffffffu, a.x, s);
        a.y += __shfl_xor_sync(0xffffffffu, a.y, s);
        a.z += __shfl_xor_sync(0xffffffffu, a.z, s);
        a.w += __shfl_xor_sync(0xffffffffu, a.w, s);
    }
}

__global__ void __launch_bounds__(256) k_gemm1(const float* __restrict__ x,
                                               const float* __restrict__ W1, int N) {
    int warpGlobal = (blockIdx.x * blockDim.x + threadIdx.x) >> 5;
    int lane = threadIdx.x & 31;
    int kg = lane & 7;
    int jg = lane >> 3;

    // W slice: rows 16kg..16kg+15, cols 4jg..4jg+3  (64 registers)
    float4 w[16];
#pragma unroll
    for (int kk = 0; kk < 16; kk++)
        w[kk] = *(const float4*)&W1[(kg * 16 + kk) * 16 + jg * 4];

    int base = warpGlobal * NPW;
    if (base >= N) return;

#pragma unroll
    for (int it = 0; it < NPW / 2; it++) {
        int n0 = base + it * 2;
        int n1 = n0 + 1;
        if (n0 >= N) break;
        bool has1 = (n1 < N);

        float4 xa[4], xb[4];
        const float4* xr0 = (const float4*)&x[(size_t)n0 * 128 + kg * 16];
#pragma unroll
        for (int i = 0; i < 4; i++) xa[i] = xr0[i];
        if (has1) {
            const float4* xr1 = (const float4*)&x[(size_t)n1 * 128 + kg * 16];
#pragma unroll
            for (int i = 0; i < 4; i++) xb[i] = xr1[i];
        } else {
#pragma unroll
            for (int i = 0; i < 4; i++) xb[i] = make_float4(0.f, 0.f, 0.f, 0.f);
        }

        float4 acc0 = make_float4(0.f, 0.f, 0.f, 0.f);
        float4 acc1 = make_float4(0.f, 0.f, 0.f, 0.f);
#pragma unroll
        for (int i = 0; i < 4; i++) {
            FMA4(acc0, xa[i].x, w[4 * i + 0]);
            FMA4(acc0, xa[i].y, w[4 * i + 1]);
            FMA4(acc0, xa[i].z, w[4 * i + 2]);
            FMA4(acc0, xa[i].w, w[4 * i + 3]);
            FMA4(acc1, xb[i].x, w[4 * i + 0]);
            FMA4(acc1, xb[i].y, w[4 * i + 1]);
            FMA4(acc1, xb[i].z, w[4 * i + 2]);
            FMA4(acc1, xb[i].w, w[4 * i + 3]);
        }

        bfly4(acc0);
        bfly4(acc1);

        if (kg == 0) {
            {
                float d = rsqrtf((float)g_deg[n0]);
                float4 v = make_float4(acc0.x * d, acc0.y * d, acc0.z * d, acc0.w * d);
                *(float4*)&g_t1[n0 * 16 + jg * 4] = v;
                *(float4*)&g_a1[n0 * 16 + jg * 4] = v;   // self-loop message
                if (jg == 0) g_dinv[n0] = d;
            }
            if (has1) {
                float d = rsqrtf((float)g_deg[n1]);
                float4 v = make_float4(acc1.x * d, acc1.y * d, acc1.z * d, acc1.w * d);
                *(float4*)&g_t1[n1 * 16 + jg * 4] = v;
                *(float4*)&g_a1[n1 * 16 + jg * 4] = v;   // self-loop message
                if (jg == 0) g_dinv[n1] = d;
            }
        }
    }
}

// ---------------- layer-1 edge scatter: 4 lanes per edge --------------------
__global__ void k_edge1(int E) {
    int t = blockIdx.x * blockDim.x + threadIdx.x;
    int e = t >> 2;
    if (e >= E) return;
    int p = t & 3;
    int2 sd = g_edge[e];
    float4 v = *(const float4*)&g_t1[sd.x * 16 + p * 4];
    red_add_v4(&g_a1[sd.y * 16 + p * 4], v);
}

// ---------------- mid: h = relu(dinv*a1+b1); t2 = (h@W2)*dinv ----------------
__global__ void k_mid(const float* __restrict__ b1, const float* __restrict__ W2, int N) {
    __shared__ float w2[32];
    __shared__ float bb[16];
    if (threadIdx.x < 32) w2[threadIdx.x] = W2[threadIdx.x];
    if (threadIdx.x < 16) bb[threadIdx.x] = b1[threadIdx.x];
    __syncthreads();

    int node = blockIdx.x * blockDim.x + threadIdx.x;
    if (node >= N) return;

    float d = g_dinv[node];
    const float4* a1 = (const float4*)&g_a1[node * 16];
    float t0 = 0.0f, t1 = 0.0f;
#pragma unroll
    for (int q = 0; q < 4; q++) {
        float4 a = a1[q];
        float h0 = fmaxf(fmaf(a.x, d, bb[q * 4 + 0]), 0.0f);
        float h1 = fmaxf(fmaf(a.y, d, bb[q * 4 + 1]), 0.0f);
        float h2 = fmaxf(fmaf(a.z, d, bb[q * 4 + 2]), 0.0f);
        float h3 = fmaxf(fmaf(a.w, d, bb[q * 4 + 3]), 0.0f);
        t0 = fmaf(h0, w2[(q * 4 + 0) * 2 + 0], t0);
        t1 = fmaf(h0, w2[(q * 4 + 0) * 2 + 1], t1);
        t0 = fmaf(h1, w2[(q * 4 + 1) * 2 + 0], t0);
        t1 = fmaf(h1, w2[(q * 4 + 1) * 2 + 1], t1);
        t0 = fmaf(h2, w2[(q * 4 + 2) * 2 + 0], t0);
        t1 = fmaf(h2, w2[(q * 4 + 2) * 2 + 1], t1);
        t0 = fmaf(h3, w2[(q * 4 + 3) * 2 + 0], t0);
        t1 = fmaf(h3, w2[(q * 4 + 3) * 2 + 1], t1);
    }
    t0 *= d; t1 *= d;
    float2 t = make_float2(t0, t1);
    *(float2*)&g_t2[node * 2] = t;
    *(float2*)&g_a2[node * 2] = t;   // self-loop message
}

// ---------------- layer-2 edge scatter: 1 thread per edge -------------------
__global__ void k_edge2(int E) {
    int e = blockIdx.x * blockDim.x + threadIdx.x;
    if (e >= E) return;
    int2 sd = g_edge[e];
    float2 v = *(const float2*)&g_t2[sd.x * 2];
    red_add_v2(&g_a2[sd.y * 2], v);
}

// ---------------- final: out = log_softmax(dinv*a2 + b2) --------------------
__global__ void k_final(const float* __restrict__ b2, float* __restrict__ out, int N) {
    int node = blockIdx.x * blockDim.x + threadIdx.x;
    if (node >= N) return;
    float d = g_dinv[node];
    float2 a = *(const float2*)&g_a2[node * 2];
    float v0 = fmaf(a.x, d, __ldg(&b2[0]));
    float v1 = fmaf(a.y, d, __ldg(&b2[1]));
    float m = fmaxf(v0, v1);
    float lse = m + logf(expf(v0 - m) + expf(v1 - m));
    float2 o = make_float2(v0 - lse, v1 - lse);
    *(float2*)&out[node * 2] = o;
}

// ---------------------------------------------------------------------------
extern "C" void kernel_launch(void* const* d_in, const int* in_sizes, int n_in,
                              void* d_out, int out_size) {
    const float* x  = (const float*)d_in[0];
    const void*  ei = d_in[1];
    const float* W1 = (const float*)d_in[2];
    const float* b1 = (const float*)d_in[3];
    const float* W2 = (const float*)d_in[4];
    const float* b2 = (const float*)d_in[5];
    float* out = (float*)d_out;

    int N = in_sizes[0] / 128;
    int E = in_sizes[1] / 2;

    const int T = 256;
    k_detect<<<1, 32>>>((const int*)ei);
    k_deg_init<<<(N + T - 1) / T, T>>>(N);
    k_convert<<<(E + T - 1) / T, T>>>(ei, E, N);

    {
        int warps = (N + NPW - 1) / NPW;
        int blocks = (warps + 7) / 8;          // 8 warps (256 threads) per block
        k_gemm1<<<blocks, 256>>>(x, W1, N);
    }

    {
        long long total = (long long)E * 4;
        int blocks = (int)((total + T - 1) / T);
        k_edge1<<<blocks, T>>>(E);
    }
    k_mid<<<(N + T - 1) / T, T>>>(b1, W2, N);
    k_edge2<<<(E + T - 1) / T, T>>>(E);
    k_final<<<(N + T - 1) / T, T>>>(b2, out, N);
}

// round 13
// speedup vs baseline: 1.1125x; 1.1125x over previous
#include <cuda_runtime.h>
#include <math.h>

#define NMAX 100000
#define EMAX 3200000
#define SCAN_B 1024

// ---------------- device scratch (static, no allocs) ------------------------
__device__ int   g_is64;
__device__ __align__(8) int2 g_edge[EMAX];   // (src, dst)
__device__ int   g_csr[EMAX];                // src ids grouped by dst
__device__ int   g_deg[NMAX];                // real in-degree (no self loop)
__device__ int   g_off[NMAX + 1];
__device__ int   g_cur[NMAX];
__device__ int   g_bsum[256];
__device__ int   g_bpre[256];
__device__ float g_dinv[NMAX];
__device__ __align__(16) float g_t1[NMAX * 16];  // (x@W1)*dinv
__device__ __align__(8)  float g_t2[NMAX * 2];   // (h@W2)*dinv

// ---------------------------------------------------------------------------
__global__ void k_detect(const int* __restrict__ ei32) {
    if (threadIdx.x == 0 && blockIdx.x == 0) {
        int all0 = 1;
        for (int i = 0; i < 64; i++)
            if (ei32[2 * i + 1] != 0) { all0 = 0; break; }
        g_is64 = all0;
    }
}

__global__ void k_deg0(int N) {
    int i = blockIdx.x * blockDim.x + threadIdx.x;
    if (i < N) g_deg[i] = 0;
}

__global__ void k_convert(const void* __restrict__ ei, int E, int N) {
    int e = blockIdx.x * blockDim.x + threadIdx.x;
    if (e >= E) return;
    int s, d;
    if (g_is64) {
        const long long* p = (const long long*)ei;
        s = (int)p[e];
        d = (int)p[(long long)E + e];
    } else {
        const int* p = (const int*)ei;
        s = p[e];
        d = p[E + e];
    }
    if ((unsigned)s >= (unsigned)N) s = 0;
    if ((unsigned)d >= (unsigned)N) d = 0;
    g_edge[e] = make_int2(s, d);
    atomicAdd(&g_deg[d], 1);
}

// ---------------- CSR build: block scan + scatter ---------------------------
__global__ void k_scan_block(int N) {
    __shared__ int sh[SCAN_B];
    int tid = threadIdx.x;
    int i = blockIdx.x * SCAN_B + tid;
    int v = (i < N) ? g_deg[i] : 0;
    sh[tid] = v;
    __syncthreads();
#pragma unroll
    for (int ofs = 1; ofs < SCAN_B; ofs <<= 1) {
        int add = (tid >= ofs) ? sh[tid - ofs] : 0;
        __syncthreads();
        sh[tid] += add;
        __syncthreads();
    }
    int incl = sh[tid];
    if (i < N) g_off[i] = incl - v;
    if (tid == SCAN_B - 1) g_bsum[blockIdx.x] = incl;
}

__global__ void k_scan_top(int nb) {
    __shared__ int sh[128];
    int tid = threadIdx.x;
    int v = (tid < nb) ? g_bsum[tid] : 0;
    sh[tid] = v;
    __syncthreads();
#pragma unroll
    for (int ofs = 1; ofs < 128; ofs <<= 1) {
        int add = (tid >= ofs) ? sh[tid - ofs] : 0;
        __syncthreads();
        sh[tid] += add;
        __syncthreads();
    }
    if (tid < nb) g_bpre[tid] = sh[tid] - v;
}

__global__ void k_scan_add(int N) {
    int i = blockIdx.x * blockDim.x + threadIdx.x;
    if (i >= N) return;
    int v = g_off[i] + g_bpre[i >> 10];
    g_off[i] = v;
    g_cur[i] = v;
    if (i == N - 1) g_off[N] = v + g_deg[i];
}

__global__ void k_scatter(int E) {
    int e = blockIdx.x * blockDim.x + threadIdx.x;
    if (e >= E) return;
    int2 sd = g_edge[e];
    int pos = atomicAdd(&g_cur[sd.y], 1);
    g_csr[pos] = sd.x;
}

// ---------------- GEMM1 (R3 design, proven): t1 = (x@W1)*dinv ---------------
__global__ void k_gemm1(const float* __restrict__ x, const float* __restrict__ W1, int N) {
    __shared__ float w[128 * 16];
    for (int i = threadIdx.x; i < 128 * 16; i += blockDim.x) w[i] = W1[i];
    __syncthreads();

    int node = blockIdx.x * blockDim.x + threadIdx.x;
    if (node >= N) return;

    float acc[16];
#pragma unroll
    for (int j = 0; j < 16; j++) acc[j] = 0.0f;

    const float4* xr = (const float4*)(x + (size_t)node * 128);
#pragma unroll 4
    for (int k4 = 0; k4 < 32; k4++) {
        float4 v = xr[k4];
        int base = k4 * 4 * 16;
#pragma unroll
        for (int j = 0; j < 16; j++) {
            float s = acc[j];
            s = fmaf(v.x, w[base + j], s);
            s = fmaf(v.y, w[base + 16 + j], s);
            s = fmaf(v.z, w[base + 32 + j], s);
            s = fmaf(v.w, w[base + 48 + j], s);
            acc[j] = s;
        }
    }

    float d = rsqrtf((float)(g_deg[node] + 1));   // +1 self loop
    g_dinv[node] = d;

    float4* t1 = (float4*)&g_t1[node * 16];
#pragma unroll
    for (int q = 0; q < 4; q++) {
        float4 t;
        t.x = acc[q * 4 + 0] * d;
        t.y = acc[q * 4 + 1] * d;
        t.z = acc[q * 4 + 2] * d;
        t.w = acc[q * 4 + 3] * d;
        t1[q] = t;
    }
}

// ---------------- layer-1 CSR gather (unroll 4) + fused relu/bias/W2 --------
__global__ void k_edge1_mid(const float* __restrict__ b1,
                            const float* __restrict__ W2, int N) {
    __shared__ float w2s[32];
    __shared__ float b1s[16];
    if (threadIdx.x < 32) w2s[threadIdx.x] = W2[threadIdx.x];
    if (threadIdx.x < 16) b1s[threadIdx.x] = b1[threadIdx.x];
    __syncthreads();

    int t = blockIdx.x * blockDim.x + threadIdx.x;
    int node = t >> 2;
    if (node >= N) return;
    int q = t & 3;

    int beg = g_off[node];
    int end = g_off[node + 1];

    float4 acc = *(const float4*)&g_t1[node * 16 + q * 4];   // self-loop message
    int i = beg;
    for (; i + 4 <= end; i += 4) {
        int s0 = __ldg(&g_csr[i]);
        int s1 = __ldg(&g_csr[i + 1]);
        int s2 = __ldg(&g_csr[i + 2]);
        int s3 = __ldg(&g_csr[i + 3]);
        float4 v0 = *(const float4*)&g_t1[s0 * 16 + q * 4];
        float4 v1 = *(const float4*)&g_t1[s1 * 16 + q * 4];
        float4 v2 = *(const float4*)&g_t1[s2 * 16 + q * 4];
        float4 v3 = *(const float4*)&g_t1[s3 * 16 + q * 4];
        acc.x += v0.x + v1.x + v2.x + v3.x;
        acc.y += v0.y + v1.y + v2.y + v3.y;
        acc.z += v0.z + v1.z + v2.z + v3.z;
        acc.w += v0.w + v1.w + v2.w + v3.w;
    }
    for (; i < end; i++) {
        int s = __ldg(&g_csr[i]);
        float4 v = *(const float4*)&g_t1[s * 16 + q * 4];
        acc.x += v.x; acc.y += v.y; acc.z += v.z; acc.w += v.w;
    }

    float d = g_dinv[node];
    float h0 = fmaxf(fmaf(acc.x, d, b1s[q * 4 + 0]), 0.0f);
    float h1 = fmaxf(fmaf(acc.y, d, b1s[q * 4 + 1]), 0.0f);
    float h2 = fmaxf(fmaf(acc.z, d, b1s[q * 4 + 2]), 0.0f);
    float h3 = fmaxf(fmaf(acc.w, d, b1s[q * 4 + 3]), 0.0f);

    float p0 = h0 * w2s[(q * 4 + 0) * 2 + 0] + h1 * w2s[(q * 4 + 1) * 2 + 0]
             + h2 * w2s[(q * 4 + 2) * 2 + 0] + h3 * w2s[(q * 4 + 3) * 2 + 0];
    float p1 = h0 * w2s[(q * 4 + 0) * 2 + 1] + h1 * w2s[(q * 4 + 1) * 2 + 1]
             + h2 * w2s[(q * 4 + 2) * 2 + 1] + h3 * w2s[(q * 4 + 3) * 2 + 1];

    p0 += __shfl_xor_sync(0xffffffffu, p0, 1);
    p0 += __shfl_xor_sync(0xffffffffu, p0, 2);
    p1 += __shfl_xor_sync(0xffffffffu, p1, 1);
    p1 += __shfl_xor_sync(0xffffffffu, p1, 2);

    if (q == 0) {
        float2 o = make_float2(p0 * d, p1 * d);
        *(float2*)&g_t2[node * 2] = o;
    }
}

// ---------------- layer-2 CSR gather (unroll 4) + fused log-softmax ---------
__global__ void k_edge2_final(const float* __restrict__ b2,
                              float* __restrict__ out, int N) {
    int node = blockIdx.x * blockDim.x + threadIdx.x;
    if (node >= N) return;

    int beg = g_off[node];
    int end = g_off[node + 1];

    float2 acc = *(const float2*)&g_t2[node * 2];   // self loop
    int i = beg;
    for (; i + 4 <= end; i += 4) {
        int s0 = __ldg(&g_csr[i]);
        int s1 = __ldg(&g_csr[i + 1]);
        int s2 = __ldg(&g_csr[i + 2]);
        int s3 = __ldg(&g_csr[i + 3]);
        float2 v0 = *(const float2*)&g_t2[s0 * 2];
        float2 v1 = *(const float2*)&g_t2[s1 * 2];
        float2 v2 = *(const float2*)&g_t2[s2 * 2];
        float2 v3 = *(const float2*)&g_t2[s3 * 2];
        acc.x += v0.x + v1.x + v2.x + v3.x;
        acc.y += v0.y + v1.y + v2.y + v3.y;
    }
    for (; i < end; i++) {
        int s = __ldg(&g_csr[i]);
        float2 v = *(const float2*)&g_t2[s * 2];
        acc.x += v.x; acc.y += v.y;
    }

    float d = g_dinv[node];
    float v0 = fmaf(acc.x, d, __ldg(&b2[0]));
    float v1 = fmaf(acc.y, d, __ldg(&b2[1]));
    float m = fmaxf(v0, v1);
    float lse = m + logf(expf(v0 - m) + expf(v1 - m));
    float2 o = make_float2(v0 - lse, v1 - lse);
    *(float2*)&out[node * 2] = o;
}

// ---------------------------------------------------------------------------
extern "C" void kernel_launch(void* const* d_in, const int* in_sizes, int n_in,
                              void* d_out, int out_size) {
    const float* x  = (const float*)d_in[0];
    const void*  ei = d_in[1];
    const float* W1 = (const float*)d_in[2];
    const float* b1 = (const float*)d_in[3];
    const float* W2 = (const float*)d_in[4];
    const float* b2 = (const float*)d_in[5];
    float* out = (float*)d_out;

    int N = in_sizes[0] / 128;
    int E = in_sizes[1] / 2;

    const int T = 256;
    int nb = (N + SCAN_B - 1) / SCAN_B;

    k_detect<<<1, 32>>>((const int*)ei);
    k_deg0<<<(N + T - 1) / T, T>>>(N);
    k_convert<<<(E + T - 1) / T, T>>>(ei, E, N);

    k_scan_block<<<nb, SCAN_B>>>(N);
    k_scan_top<<<1, 128>>>(nb);
    k_scan_add<<<(N + T - 1) / T, T>>>(N);
    k_scatter<<<(E + T - 1) / T, T>>>(E);

    k_gemm1<<<(N + T - 1) / T, T>>>(x, W1, N);

    k_edge1_mid<<<(N * 4 + T - 1) / T, T>>>(b1, W2, N);
    k_edge2_final<<<(N + T - 1) / T, T>>>(b2, out, N);
}